// round 5
// baseline (speedup 1.0000x reference)
#include <cuda_runtime.h>
#include <cuda_bf16.h>
#include <math.h>

#define BB 16
#define CC 256
#define HH 96
#define WW 128
#define HW (HH * WW)          // 12288
#define HW4 (HW / 4)          // 3072 float4 per plane
#define OUT_H 12
#define OUT_W 16
#define NN (OUT_H * OUT_W)    // 192
#define KH 8
#define KW 8
#define QQ 4
#define HIDDEN 128
#define TAU_INV 10.0f

#define SCALE_BLOCKS 16
#define SEGS 6                          // 6 segments x 2048 elems per plane
#define FUSE_BLOCKS (BB * CC * SEGS)    // 24576
#define TOTAL_BLOCKS (SCALE_BLOCKS + FUSE_BLOCKS)

// ---------------- device scratch (static, zero-initialized) ----------------
__device__ float    g_scale[BB * CC];   // zero-init; written only when Wb != 0
__device__ int      g_viol;             // bit0: some row NOT diagonal; bit1: Wb nonzero
__device__ unsigned g_acnt;             // analysis barrier counter (scale blocks)
__device__ unsigned g_scnt;             // pipeline completion counter (scale blocks)
__device__ unsigned g_ready;            // g_scale valid (or known-unneeded/zero)
__device__ unsigned g_done;             // whole-grid completion counter

__device__ __forceinline__ float sigmoidf_(float z) {
    return __fdividef(1.0f, 1.0f + __expf(-z));
}

__global__ void __launch_bounds__(256) mono_kernel(const float* __restrict__ x,
                                                   const float* __restrict__ wf,
                                                   const float* __restrict__ w1,
                                                   const float* __restrict__ w2,
                                                   float* __restrict__ out) {
    int bid = blockIdx.x;
    int tid = threadIdx.x;

    if (bid < SCALE_BLOCKS) {
        // ================= scale role: analysis + (slow-path) pipeline =================
        int b = bid;
        // analyze rows [b*16, b*16+16): 2 elements per thread per row
        {
            int viol = 0;
            #pragma unroll 4
            for (int r = 0; r < 16; r++) {
                int c = b * 16 + r;
                float a0 = wf[c * 512 + tid];        // Wa[c, tid]
                float a1 = wf[c * 512 + 256 + tid];  // Wb[c, tid]
                if (a0 != 0.0f && tid != c) viol |= 1;
                if (a1 != 0.0f) { viol |= 2; if (tid != c) viol |= 1; }
            }
            viol = __syncthreads_or(viol);
            if (tid == 0) {
                if (viol) atomicOr(&g_viol, viol);
                __threadfence();
                atomicAdd(&g_acnt, 1u);
                while (atomicAdd(&g_acnt, 0u) < SCALE_BLOCKS) { }
            }
            __syncthreads();
        }
        int viol = g_viol;
        if ((viol & 2) == 0) {
            // scale unused everywhere (db==0 for all rows); publish zeros as valid
            if (tid == 0 && b == 0) { __threadfence(); atomicExch(&g_ready, 1u); }
        } else {
            // full soft-quantile pipeline for batch b (correctness-grade)
            __shared__ float s[NN];
            __shared__ float rr[NN];
            __shared__ float2 red[256];
            __shared__ float qv[CC * QQ];
            __shared__ float ts[HIDDEN * QQ];
            const float quant[QQ] = {0.25f, 0.5f, 0.75f, 0.95f};

            for (int c = 0; c < CC; c++) {
                int bc = b * CC + c;
                if (tid < NN) {
                    int oh = tid >> 4, ow = tid & 15;
                    const float* base = x + (size_t)bc * HW + oh * (KH * WW) + ow * KW;
                    float acc = 0.0f;
                    #pragma unroll
                    for (int r = 0; r < KH; r++) {
                        float4 a = *(const float4*)(base + r * WW);
                        float4 bb = *(const float4*)(base + r * WW + 4);
                        acc += a.x + a.y + a.z + a.w + bb.x + bb.y + bb.z + bb.w;
                    }
                    s[tid] = acc * (1.0f / 64.0f);
                }
                __syncthreads();
                if (tid < NN) {
                    float xi = s[tid];
                    float acc = 1.0f;
                    #pragma unroll 4
                    for (int j = 0; j < NN; j++) acc += sigmoidf_((xi - s[j]) * TAU_INV);
                    rr[tid] = acc;
                }
                __syncthreads();
                for (int q = 0; q < QQ; q++) {
                    float tq = 1.0f + quant[q] * (float)(NN - 1);
                    float e = 0.0f, ex = 0.0f;
                    if (tid < NN) {
                        e  = __expf(-fabsf(rr[tid] - tq) * TAU_INV);
                        ex = e * s[tid];
                    }
                    red[tid] = make_float2(e, ex);
                    __syncthreads();
                    for (int st = 128; st >= 1; st >>= 1) {
                        if (tid < st) {
                            float2 o = red[tid + st];
                            red[tid].x += o.x;
                            red[tid].y += o.y;
                        }
                        __syncthreads();
                    }
                    if (tid == 0) qv[c * QQ + q] = red[0].y / red[0].x;
                    __syncthreads();
                }
            }
            for (int idx = tid; idx < HIDDEN * QQ; idx += 256) {
                int h = idx >> 2, q = idx & 3;
                float acc = 0.0f;
                #pragma unroll 4
                for (int c = 0; c < CC; c++) acc += w1[h * CC + c] * qv[c * QQ + q];
                ts[idx] = fmaxf(acc, 0.0f);
            }
            __syncthreads();
            {
                int c = tid;
                float acc = 0.0f;
                #pragma unroll 4
                for (int k = 0; k < HIDDEN * QQ; k++) acc += ts[k] * w2[c * (HIDDEN * QQ) + k];
                g_scale[b * CC + c] = sigmoidf_(acc);
            }
            __syncthreads();
            if (tid == 0) {
                __threadfence();
                if (atomicAdd(&g_scnt, 1u) == SCALE_BLOCKS - 1) atomicExch(&g_ready, 1u);
            }
        }
    } else {
        // ================= fuse role: per-row self-analysis + stream/matvec =================
        int fid   = bid - SCALE_BLOCKS;
        int plane = fid / SEGS;                  // b*C + c
        int seg   = fid % SEGS;
        int b = plane >> 8;
        int c = plane & (CC - 1);

        __shared__ float sh_dadb[2];
        __shared__ float Ms[CC];

        // row analysis: Wa[c,tid], Wb[c,tid]
        float wa = wf[c * 512 + tid];
        float wb = wf[c * 512 + 256 + tid];
        int bad = ((wa != 0.0f) && (tid != c)) || ((wb != 0.0f) && (tid != c));
        int nondiag = __syncthreads_or(bad);
        if (tid == c) { sh_dadb[0] = wa; sh_dadb[1] = wb; }
        __syncthreads();

        size_t off = (size_t)plane * HW4 + seg * 512 + tid;
        const float4* src = (const float4*)x + off;
        float4*       dst = (float4*)out      + off;

        if (!nondiag) {
            float da = sh_dadb[0], db = sh_dadb[1];
            float coeff;
            if (db != 0.0f) {
                if (tid == 0) { while (atomicAdd(&g_ready, 0u) == 0u) { } }
                __syncthreads();
                __threadfence();
                coeff = da + db * g_scale[plane];
            } else {
                coeff = da;
            }
            float4 v0 = __ldcs(src);
            float4 v1 = __ldcs(src + 256);
            v0.x *= coeff; v0.y *= coeff; v0.z *= coeff; v0.w *= coeff;
            v1.x *= coeff; v1.y *= coeff; v1.z *= coeff; v1.w *= coeff;
            __stcs(dst,       v0);
            __stcs(dst + 256, v1);
        } else {
            // general per-row matvec: out[b,c,p] = sum_k (Wa[c,k]+Wb[c,k]*scale[b,k])*x[b,k,p]
            if (tid == 0) { while (atomicAdd(&g_ready, 0u) == 0u) { } }
            __syncthreads();
            __threadfence();
            Ms[tid] = wa + wb * g_scale[b * CC + tid];
            __syncthreads();

            const float4* xb4 = (const float4*)x + (size_t)b * CC * HW4 + seg * 512 + tid;
            float4 a0 = make_float4(0.f, 0.f, 0.f, 0.f);
            float4 a1 = make_float4(0.f, 0.f, 0.f, 0.f);
            for (int k = 0; k < CC; k++) {
                float m = Ms[k];
                float4 v0 = xb4[(size_t)k * HW4];
                float4 v1 = xb4[(size_t)k * HW4 + 256];
                a0.x += m * v0.x; a0.y += m * v0.y; a0.z += m * v0.z; a0.w += m * v0.w;
                a1.x += m * v1.x; a1.y += m * v1.y; a1.z += m * v1.z; a1.w += m * v1.w;
            }
            dst[0]   = a0;
            dst[256] = a1;
        }
    }

    // last finishing block resets per-call state for the next graph replay
    __syncthreads();
    if (threadIdx.x == 0) {
        __threadfence();
        if (atomicAdd(&g_done, 1u) == (unsigned)(gridDim.x - 1)) {
            g_viol  = 0;
            g_acnt  = 0;
            g_scnt  = 0;
            g_ready = 0;
            g_done  = 0;
            __threadfence();
        }
    }
}

// ---------------- launch ----------------
extern "C" void kernel_launch(void* const* d_in, const int* in_sizes, int n_in,
                              void* d_out, int out_size) {
    const float* x  = (const float*)d_in[0];
    const float* w1 = (const float*)d_in[1];
    const float* w2 = (const float*)d_in[2];
    const float* wf = (const float*)d_in[3];
    float* out = (float*)d_out;

    mono_kernel<<<TOTAL_BLOCKS, 256>>>(x, wf, w1, w2, out);
}

// round 6
// speedup vs baseline: 1.1244x; 1.1244x over previous
#include <cuda_runtime.h>
#include <cuda_bf16.h>
#include <math.h>

#define BB 16
#define CC 256
#define HH 96
#define WW 128
#define HW (HH * WW)          // 12288
#define HW4 (HW / 4)          // 3072 float4 per plane
#define OUT_H 12
#define OUT_W 16
#define NN (OUT_H * OUT_W)    // 192
#define KH 8
#define KW 8
#define QQ 4
#define HIDDEN 128
#define TAU_INV 10.0f

#define SCALE_BLOCKS 16
#define SEGS 6                          // 6 segments x 512 float4 per plane
#define FUSE_BLOCKS (BB * CC * SEGS)    // 24576
#define TOTAL_BLOCKS (SCALE_BLOCKS + FUSE_BLOCKS)

// ---------------- device scratch (static, zero-initialized) ----------------
__device__ float    g_scale[BB * CC];   // zero-init; written only when Wb != 0
__device__ int      g_viol;             // bit0: some row NOT diagonal; bit1: Wb nonzero
__device__ unsigned g_acnt;             // analysis barrier counter (scale blocks)
__device__ unsigned g_scnt;             // pipeline completion counter (scale blocks)
__device__ unsigned g_ready;            // g_scale valid (or known-unneeded/zero)
__device__ unsigned g_done;             // whole-grid completion counter

__device__ __forceinline__ float sigmoidf_(float z) {
    return __fdividef(1.0f, 1.0f + __expf(-z));
}

// shared-memory overlay: scale role needs the big buffers, fuse role the small ones
union SmemU {
    struct {
        float  s[NN];
        float  rr[NN];
        float2 red[256];
        float  qv[CC * QQ];
        float  ts[HIDDEN * QQ];
    } sc;
    struct {
        float dadb[2];
        float Ms[CC];
    } fu;
};

__global__ void __launch_bounds__(256, 8) mono_kernel(const float* __restrict__ x,
                                                      const float* __restrict__ wf,
                                                      const float* __restrict__ w1,
                                                      const float* __restrict__ w2,
                                                      float* __restrict__ out) {
    __shared__ SmemU sm;
    int bid = blockIdx.x;
    int tid = threadIdx.x;

    if (bid >= SCALE_BLOCKS) {
        // ================= fuse role =================
        int fid   = bid - SCALE_BLOCKS;
        int plane = fid / SEGS;                  // b*C + c
        int seg   = fid % SEGS;
        int b = plane >> 8;
        int c = plane & (CC - 1);

        size_t off = (size_t)plane * HW4 + seg * 512 + tid;
        const float4* src = (const float4*)x + off;
        float4*       dst = (float4*)out      + off;

        // 1) issue streaming loads FIRST — they fly while we analyze the wf row
        float4 v0 = __ldcs(src);
        float4 v1 = __ldcs(src + 256);

        // 2) row analysis (wf row is L2-resident after first touch)
        float wa = wf[c * 512 + tid];
        float wb = wf[c * 512 + 256 + tid];
        int bad = ((wa != 0.0f) | (wb != 0.0f)) & (tid != c);
        if (tid == c) { sm.fu.dadb[0] = wa; sm.fu.dadb[1] = wb; }
        int nondiag = __syncthreads_or(bad);

        if (!nondiag) {
            float da = sm.fu.dadb[0], db = sm.fu.dadb[1];
            float coeff;
            if (db != 0.0f) {
                if (tid == 0) { while (atomicAdd(&g_ready, 0u) == 0u) { } }
                __syncthreads();
                __threadfence();
                coeff = da + db * g_scale[plane];
            } else {
                coeff = da;
            }
            v0.x *= coeff; v0.y *= coeff; v0.z *= coeff; v0.w *= coeff;
            v1.x *= coeff; v1.y *= coeff; v1.z *= coeff; v1.w *= coeff;
            __stcs(dst,       v0);
            __stcs(dst + 256, v1);
        } else {
            // general per-row matvec (correctness-grade; may spill under reg cap)
            if (tid == 0) { while (atomicAdd(&g_ready, 0u) == 0u) { } }
            __syncthreads();
            __threadfence();
            sm.fu.Ms[tid] = wa + wb * g_scale[b * CC + tid];
            __syncthreads();

            const float4* xb4 = (const float4*)x + (size_t)b * CC * HW4 + seg * 512 + tid;
            float4 a0 = make_float4(0.f, 0.f, 0.f, 0.f);
            float4 a1 = make_float4(0.f, 0.f, 0.f, 0.f);
            for (int k = 0; k < CC; k++) {
                float m = sm.fu.Ms[k];
                float4 u0 = xb4[(size_t)k * HW4];
                float4 u1 = xb4[(size_t)k * HW4 + 256];
                a0.x += m * u0.x; a0.y += m * u0.y; a0.z += m * u0.z; a0.w += m * u0.w;
                a1.x += m * u1.x; a1.y += m * u1.y; a1.z += m * u1.z; a1.w += m * u1.w;
            }
            dst[0]   = a0;
            dst[256] = a1;
        }
    } else {
        // ================= scale role: analysis + (slow-path) pipeline =================
        int b = bid;
        {
            int viol = 0;
            #pragma unroll 4
            for (int r = 0; r < 16; r++) {
                int c = b * 16 + r;
                float a0 = wf[c * 512 + tid];
                float a1 = wf[c * 512 + 256 + tid];
                if (a0 != 0.0f && tid != c) viol |= 1;
                if (a1 != 0.0f) { viol |= 2; if (tid != c) viol |= 1; }
            }
            viol = __syncthreads_or(viol);
            if (tid == 0) {
                if (viol) atomicOr(&g_viol, viol);
                __threadfence();
                atomicAdd(&g_acnt, 1u);
                while (atomicAdd(&g_acnt, 0u) < SCALE_BLOCKS) { }
            }
            __syncthreads();
        }
        int viol = g_viol;
        if ((viol & 2) == 0) {
            if (tid == 0 && b == 0) { __threadfence(); atomicExch(&g_ready, 1u); }
        } else {
            const float quant[QQ] = {0.25f, 0.5f, 0.75f, 0.95f};
            for (int c = 0; c < CC; c++) {
                int bc = b * CC + c;
                if (tid < NN) {
                    int oh = tid >> 4, ow = tid & 15;
                    const float* base = x + (size_t)bc * HW + oh * (KH * WW) + ow * KW;
                    float acc = 0.0f;
                    #pragma unroll
                    for (int r = 0; r < KH; r++) {
                        float4 a = *(const float4*)(base + r * WW);
                        float4 bb = *(const float4*)(base + r * WW + 4);
                        acc += a.x + a.y + a.z + a.w + bb.x + bb.y + bb.z + bb.w;
                    }
                    sm.sc.s[tid] = acc * (1.0f / 64.0f);
                }
                __syncthreads();
                if (tid < NN) {
                    float xi = sm.sc.s[tid];
                    float acc = 1.0f;
                    #pragma unroll 4
                    for (int j = 0; j < NN; j++) acc += sigmoidf_((xi - sm.sc.s[j]) * TAU_INV);
                    sm.sc.rr[tid] = acc;
                }
                __syncthreads();
                for (int q = 0; q < QQ; q++) {
                    float tq = 1.0f + quant[q] * (float)(NN - 1);
                    float e = 0.0f, ex = 0.0f;
                    if (tid < NN) {
                        e  = __expf(-fabsf(sm.sc.rr[tid] - tq) * TAU_INV);
                        ex = e * sm.sc.s[tid];
                    }
                    sm.sc.red[tid] = make_float2(e, ex);
                    __syncthreads();
                    for (int st = 128; st >= 1; st >>= 1) {
                        if (tid < st) {
                            float2 o = sm.sc.red[tid + st];
                            sm.sc.red[tid].x += o.x;
                            sm.sc.red[tid].y += o.y;
                        }
                        __syncthreads();
                    }
                    if (tid == 0) sm.sc.qv[c * QQ + q] = sm.sc.red[0].y / sm.sc.red[0].x;
                    __syncthreads();
                }
            }
            for (int idx = tid; idx < HIDDEN * QQ; idx += 256) {
                int h = idx >> 2, q = idx & 3;
                float acc = 0.0f;
                #pragma unroll 4
                for (int c = 0; c < CC; c++) acc += w1[h * CC + c] * sm.sc.qv[c * QQ + q];
                sm.sc.ts[idx] = fmaxf(acc, 0.0f);
            }
            __syncthreads();
            {
                int c = tid;
                float acc = 0.0f;
                #pragma unroll 4
                for (int k = 0; k < HIDDEN * QQ; k++) acc += sm.sc.ts[k] * w2[c * (HIDDEN * QQ) + k];
                g_scale[b * CC + c] = sigmoidf_(acc);
            }
            __syncthreads();
            if (tid == 0) {
                __threadfence();
                if (atomicAdd(&g_scnt, 1u) == SCALE_BLOCKS - 1) atomicExch(&g_ready, 1u);
            }
        }
    }

    // last finishing block resets per-call state for the next graph replay
    __syncthreads();
    if (threadIdx.x == 0) {
        __threadfence();
        if (atomicAdd(&g_done, 1u) == (unsigned)(gridDim.x - 1)) {
            g_viol  = 0;
            g_acnt  = 0;
            g_scnt  = 0;
            g_ready = 0;
            g_done  = 0;
            __threadfence();
        }
    }
}

// ---------------- launch ----------------
extern "C" void kernel_launch(void* const* d_in, const int* in_sizes, int n_in,
                              void* d_out, int out_size) {
    const float* x  = (const float*)d_in[0];
    const float* w1 = (const float*)d_in[1];
    const float* w2 = (const float*)d_in[2];
    const float* wf = (const float*)d_in[3];
    float* out = (float*)d_out;

    mono_kernel<<<TOTAL_BLOCKS, 256>>>(x, w1 ? wf : wf, w1, w2, out);
}